// round 4
// baseline (speedup 1.0000x reference)
#include <cuda_runtime.h>
#include <cuda_bf16.h>
#include <cstdint>

// Problem constants (fixed by setup_inputs)
#define T_TOK   8192      // B*S = 4*2048
#define D_IN    2048
#define D_OUT   2048
#define R_RANK  64
#define N_EXP   16
#define N_COLS  80        // R + E combined small-GEMM width

// ---------------- device scratch (no allocations allowed) ----------------
__device__ float g_S[T_TOK * N_COLS];        // [token][0..63]=res_hidden, [64..79]=router logits
__device__ int   g_cnt[N_EXP];
__device__ int   g_tok[N_EXP * T_TOK];
__device__ float g_wt [N_EXP * T_TOK];
// hi/lo bf16 copies for the tensor-core base GEMM
__device__ __nv_bfloat16 g_xhi[T_TOK * D_IN];
__device__ __nv_bfloat16 g_xlo[T_TOK * D_IN];
__device__ __nv_bfloat16 g_whi[D_OUT * D_IN];
__device__ __nv_bfloat16 g_wlo[D_OUT * D_IN];

// ---------------- helpers ----------------
__device__ __forceinline__ uint32_t smem_u32(const void* p) {
    uint32_t a;
    asm("{ .reg .u64 t; cvta.to.shared.u64 t, %1; cvt.u32.u64 %0, t; }" : "=r"(a) : "l"(p));
    return a;
}
__device__ __forceinline__ void cp16(uint32_t s, const void* g) {
    asm volatile("cp.async.cg.shared.global [%0], [%1], 16;" :: "r"(s), "l"(g) : "memory");
}
__device__ __forceinline__ uint32_t lds32(uint32_t addr) {
    uint32_t v;
    asm volatile("ld.shared.b32 %0, [%1];" : "=r"(v) : "r"(addr));
    return v;
}
__device__ __forceinline__ void mma16816(float* c, const uint32_t* a, uint32_t b0, uint32_t b1) {
    asm volatile(
        "mma.sync.aligned.m16n8k16.row.col.f32.bf16.bf16.f32 "
        "{%0,%1,%2,%3}, {%4,%5,%6,%7}, {%8,%9}, {%0,%1,%2,%3};"
        : "+f"(c[0]), "+f"(c[1]), "+f"(c[2]), "+f"(c[3])
        : "r"(a[0]), "r"(a[1]), "r"(a[2]), "r"(a[3]), "r"(b0), "r"(b1));
}
__device__ __forceinline__ void red_v4(float* p, float x, float y, float z, float w) {
    asm volatile("red.global.add.v4.f32 [%0], {%1,%2,%3,%4};"
                 :: "l"(p), "f"(x), "f"(y), "f"(z), "f"(w) : "memory");
}
#define CP_COMMIT() asm volatile("cp.async.commit_group;" ::: "memory")
#define CP_WAIT(n)  asm volatile("cp.async.wait_group %0;" :: "n"(n) : "memory")

// ============================================================================
// Kernel 0: fp32 -> (hi, lo) bf16 split
// ============================================================================
__global__ __launch_bounds__(256) void k0_convert(
    const float* __restrict__ src, __nv_bfloat16* __restrict__ hi,
    __nv_bfloat16* __restrict__ lo, int n4)
{
    int i = blockIdx.x * blockDim.x + threadIdx.x;
    if (i >= n4) return;
    float4 v = *(const float4*)&src[(size_t)i * 4];
    __nv_bfloat16 h[4], l[4];
    float vv[4] = {v.x, v.y, v.z, v.w};
#pragma unroll
    for (int j = 0; j < 4; j++) {
        h[j] = __float2bfloat16_rn(vv[j]);
        l[j] = __float2bfloat16_rn(vv[j] - __bfloat162float(h[j]));
    }
    *(uint2*)&hi[(size_t)i * 4] = *(uint2*)h;
    *(uint2*)&lo[(size_t)i * 4] = *(uint2*)l;
}

// ============================================================================
// Kernel 1: S = x @ [A^T | W_router^T]  (fp32 SIMT)
// ============================================================================
__global__ __launch_bounds__(256) void k1_small_gemm(
    const float* __restrict__ x,
    const float* __restrict__ A,
    const float* __restrict__ Wr)
{
    __shared__ float xs[128][68];
    __shared__ float ws[40][68];

    const int tid = threadIdx.x;
    if (blockIdx.x == 0 && blockIdx.y == 0 && tid < N_EXP) g_cnt[tid] = 0;

    const int m0 = blockIdx.y * 128;
    const int c0 = blockIdx.x * 40;
    const int tg = tid >> 3;
    const int cg = tid & 7;

    float acc[4][5];
#pragma unroll
    for (int i = 0; i < 4; i++)
#pragma unroll
        for (int j = 0; j < 5; j++) acc[i][j] = 0.f;

    for (int k0 = 0; k0 < D_IN; k0 += 64) {
#pragma unroll
        for (int it = 0; it < 8; it++) {
            int q = tid + it * 256;
            int row = q >> 4;
            int kc = (q & 15) << 2;
            float4 v = *(const float4*)&x[(size_t)(m0 + row) * D_IN + k0 + kc];
            *(float4*)&xs[row][kc] = v;
        }
        for (int q = tid; q < 40 * 16; q += 256) {
            int col = q >> 4;
            int kc = (q & 15) << 2;
            int gc = c0 + col;
            const float* src = (gc < R_RANK) ? (A + (size_t)gc * D_IN)
                                             : (Wr + (size_t)(gc - R_RANK) * D_IN);
            float4 v = *(const float4*)&src[k0 + kc];
            *(float4*)&ws[col][kc] = v;
        }
        __syncthreads();

#pragma unroll 16
        for (int kk = 0; kk < 64; kk++) {
            float av[4], bv[5];
#pragma unroll
            for (int i = 0; i < 4; i++) av[i] = xs[tg * 4 + i][kk];
#pragma unroll
            for (int j = 0; j < 5; j++) bv[j] = ws[cg * 5 + j][kk];
#pragma unroll
            for (int i = 0; i < 4; i++)
#pragma unroll
                for (int j = 0; j < 5; j++) acc[i][j] += av[i] * bv[j];
        }
        __syncthreads();
    }

#pragma unroll
    for (int i = 0; i < 4; i++) {
        size_t base = (size_t)(m0 + tg * 4 + i) * N_COLS + c0 + cg * 5;
#pragma unroll
        for (int j = 0; j < 5; j++) g_S[base + j] = acc[i][j];
    }
}

// ============================================================================
// Kernel 2: softmax + top-k + scatter
// ============================================================================
__global__ __launch_bounds__(128) void k2_router(const int* __restrict__ topk_ptr)
{
    int t = blockIdx.x * blockDim.x + threadIdx.x;
    if (t >= T_TOK) return;

    float p[N_EXP];
    float mx = -1e30f;
#pragma unroll
    for (int e = 0; e < N_EXP; e++) {
        p[e] = g_S[(size_t)t * N_COLS + R_RANK + e];
        mx = fmaxf(mx, p[e]);
    }
    float sum = 0.f;
#pragma unroll
    for (int e = 0; e < N_EXP; e++) { p[e] = __expf(p[e] - mx); sum += p[e]; }
    float inv = 1.f / sum;
#pragma unroll
    for (int e = 0; e < N_EXP; e++) p[e] *= inv;

    int k = topk_ptr ? *topk_ptr : 2;

    if (k > 0 && k < N_EXP) {
        unsigned sel = 0;
        float ssum = 0.f;
        for (int it = 0; it < k; it++) {
            int best = -1; float bv = -1.f;
#pragma unroll
            for (int e = 0; e < N_EXP; e++)
                if (!((sel >> e) & 1u) && p[e] > bv) { bv = p[e]; best = e; }
            sel |= 1u << best;
            ssum += bv;
        }
        float denom = 1.f / (ssum + 1e-6f);
#pragma unroll
        for (int e = 0; e < N_EXP; e++) {
            if ((sel >> e) & 1u) {
                float w = p[e] * denom;
                int slot = atomicAdd(&g_cnt[e], 1);
                g_tok[e * T_TOK + slot] = t;
                g_wt [e * T_TOK + slot] = w;
            }
        }
    } else {
#pragma unroll
        for (int e = 0; e < N_EXP; e++) {
            int slot = atomicAdd(&g_cnt[e], 1);
            g_tok[e * T_TOK + slot] = t;
            g_wt [e * T_TOK + slot] = p[e];
        }
    }
}

// ============================================================================
// Kernel 3: base GEMM via mma.sync bf16 hi/lo (3-term accumulation)
// CTA tile 128x256, BK=32, 8 warps (2x4), warp tile 64x64, 3-stage cp.async.
// smem row stride 80B -> conflict-free.
// ============================================================================
#define BK        32
#define NCHUNK    (D_IN / BK)                 // 64
#define MAT_A_B   (128 * 80)                  // 10240
#define MAT_B_B   (256 * 80)                  // 20480
#define STAGE_B   (2 * MAT_A_B + 2 * MAT_B_B) // 61440
#define SMEM_K3   (3 * STAGE_B)               // 184320

__global__ __launch_bounds__(256, 1) void k3_mma_gemm(
    const float* __restrict__ bias, float* __restrict__ out)
{
    extern __shared__ char sm[];
    const int tid  = threadIdx.x;
    const int wid  = tid >> 5;
    const int lane = tid & 31;
    const int g    = lane >> 2;      // 0..7
    const int t4   = lane & 3;       // 0..3

    const int m0 = blockIdx.y * 128;
    const int n0 = blockIdx.x * 256;
    const int wm = (wid >> 2) * 64;  // warp M offset
    const int wn = (wid & 3) * 64;   // warp N offset

    const uint32_t sbase = smem_u32(sm);

    float acc[4][8][4];
#pragma unroll
    for (int mi = 0; mi < 4; mi++)
#pragma unroll
        for (int ni = 0; ni < 8; ni++)
#pragma unroll
            for (int r = 0; r < 4; r++) acc[mi][ni][r] = 0.f;

    // ---- async load of one k-chunk into stage c%3 ----
    auto load_chunk = [&](int c) {
        const uint32_t stg = sbase + (c % 3) * STAGE_B;
        const int k0 = c * BK;
#pragma unroll
        for (int it = 0; it < 12; it++) {
            int q = tid + it * 256;          // 0..3071
            if (q < 1024) {                  // A: Ahi | Alo
                int mat  = q >> 9;
                int row  = (q >> 2) & 127;
                int quad = q & 3;
                const __nv_bfloat16* src = mat ? g_xlo : g_xhi;
                cp16(stg + mat * MAT_A_B + row * 80 + quad * 16,
                     &src[(size_t)(m0 + row) * D_IN + k0 + quad * 8]);
            } else {                         // B: Bhi | Blo
                int q2   = q - 1024;
                int mat  = q2 >> 10;
                int row  = (q2 >> 2) & 255;
                int quad = q2 & 3;
                const __nv_bfloat16* src = mat ? g_wlo : g_whi;
                cp16(stg + 2 * MAT_A_B + mat * MAT_B_B + row * 80 + quad * 16,
                     &src[(size_t)(n0 + row) * D_IN + k0 + quad * 8]);
            }
        }
        CP_COMMIT();
    };

    load_chunk(0);
    load_chunk(1);

    for (int c = 0; c < NCHUNK; c++) {
        if (c + 2 < NCHUNK) { load_chunk(c + 2); CP_WAIT(2); }
        else if (c + 1 < NCHUNK) { CP_WAIT(1); }
        else { CP_WAIT(0); }
        __syncthreads();

        const uint32_t stg = sbase + (c % 3) * STAGE_B;
        const uint32_t sAh = stg;
        const uint32_t sAl = stg + MAT_A_B;
        const uint32_t sBh = stg + 2 * MAT_A_B;
        const uint32_t sBl = stg + 2 * MAT_A_B + MAT_B_B;

#pragma unroll
        for (int ks = 0; ks < 2; ks++) {
            const uint32_t kb = ks * 32 + t4 * 4;

            uint32_t aH[4][4], aL[4][4];
#pragma unroll
            for (int mi = 0; mi < 4; mi++) {
                uint32_t ab = (uint32_t)((wm + mi * 16 + g) * 80) + kb;
                aH[mi][0] = lds32(sAh + ab);
                aH[mi][1] = lds32(sAh + ab + 8 * 80);
                aH[mi][2] = lds32(sAh + ab + 16);
                aH[mi][3] = lds32(sAh + ab + 8 * 80 + 16);
                aL[mi][0] = lds32(sAl + ab);
                aL[mi][1] = lds32(sAl + ab + 8 * 80);
                aL[mi][2] = lds32(sAl + ab + 16);
                aL[mi][3] = lds32(sAl + ab + 8 * 80 + 16);
            }
#pragma unroll
            for (int ni = 0; ni < 8; ni++) {
                uint32_t bb = (uint32_t)((wn + ni * 8 + g) * 80) + kb;
                uint32_t bh0 = lds32(sBh + bb), bh1 = lds32(sBh + bb + 16);
                uint32_t bl0 = lds32(sBl + bb), bl1 = lds32(sBl + bb + 16);
#pragma unroll
                for (int mi = 0; mi < 4; mi++) {
                    mma16816(acc[mi][ni], aH[mi], bh0, bh1);   // hi*hi
                    mma16816(acc[mi][ni], aH[mi], bl0, bl1);   // hi*lo
                    mma16816(acc[mi][ni], aL[mi], bh0, bh1);   // lo*hi
                }
            }
        }
        __syncthreads();
    }

    // ---- epilogue: bias add + store ----
#pragma unroll
    for (int mi = 0; mi < 4; mi++) {
        int row = m0 + wm + mi * 16 + g;
#pragma unroll
        for (int ni = 0; ni < 8; ni++) {
            int col = n0 + wn + ni * 8 + t4 * 2;
            float2 bv = *(const float2*)&bias[col];
            float2 o0, o1;
            o0.x = acc[mi][ni][0] + bv.x;
            o0.y = acc[mi][ni][1] + bv.y;
            o1.x = acc[mi][ni][2] + bv.x;
            o1.y = acc[mi][ni][3] + bv.y;
            *(float2*)&out[(size_t)row * D_OUT + col]       = o0;
            *(float2*)&out[(size_t)(row + 8) * D_OUT + col] = o1;
        }
    }
}

// ============================================================================
// Kernel 4: delta — expert-grouped, block = (expert, 64-token tile), d-loop
// inside (H loaded once). 4 tok x 8 d microtile. red.v4 accumulation.
// ============================================================================
#define HS_STRIDE  68
#define BS_STRIDE  132
#define K4_SMEM    (64 * HS_STRIDE * 4 + 64 * BS_STRIDE * 4 + 64 * 4)  // 51968

__global__ __launch_bounds__(256) void k4_delta(
    const float* __restrict__ Bm,
    float* __restrict__ out)
{
    extern __shared__ float sm4[];
    float* Hs  = sm4;                          // [64][HS_STRIDE]  (r-major, w-scaled)
    float* Bsh = sm4 + 64 * HS_STRIDE;         // [64][BS_STRIDE]  (r-major)
    int*   stok = (int*)(sm4 + 64 * HS_STRIDE + 64 * BS_STRIDE);

    const int e     = blockIdx.x >> 5;         // 16 experts
    const int stile = blockIdx.x & 31;         // 32 token tiles
    const int cnt   = g_cnt[e];
    const int tid   = threadIdx.x;

    if (stile * 64 >= cnt) return;

    const int a = tid >> 4;    // 0..15 token group (4 tokens)
    const int b = tid & 15;    // 0..15 d group (8 d)

    for (int s0 = stile * 64; s0 < cnt; s0 += 32 * 64) {
        // ---- load H tile (64 slots x 64 r), transpose, scale by weight ----
#pragma unroll
        for (int it = 0; it < 4; it++) {
            int q    = tid + it * 256;
            int slot = q >> 4;
            int r4   = (q & 15) << 2;
            int s    = s0 + slot;
            float4 v = make_float4(0.f, 0.f, 0.f, 0.f);
            float  w = 0.f;
            int    t = -1;
            if (s < cnt) {
                t = g_tok[e * T_TOK + s];
                w = g_wt [e * T_TOK + s];
                v = *(const float4*)&g_S[(size_t)t * N_COLS + r4];
            }
            Hs[(r4 + 0) * HS_STRIDE + slot] = v.x * w;
            Hs[(r4 + 1) * HS_STRIDE + slot] = v.y * w;
            Hs[(r4 + 2) * HS_STRIDE + slot] = v.z * w;
            Hs[(r4 + 3) * HS_STRIDE + slot] = v.w * w;
            if (r4 == 0) stok[slot] = t;
        }
        __syncthreads();

        for (int d0 = 0; d0 < D_OUT; d0 += 128) {
            // ---- load B chunk (128 d x 64 r), transpose into [r][d] ----
            // mapping: d = q&127 (contiguous in warp -> conflict-free STS),
            //          r4 = (q>>7)*4
#pragma unroll
            for (int it = 0; it < 8; it++) {
                int q  = tid + it * 256;
                int d  = q & 127;
                int r4 = (q >> 7) << 2;
                float4 v = *(const float4*)&Bm[((size_t)e * D_OUT + d0 + d) * R_RANK + r4];
                Bsh[(r4 + 0) * BS_STRIDE + d] = v.x;
                Bsh[(r4 + 1) * BS_STRIDE + d] = v.y;
                Bsh[(r4 + 2) * BS_STRIDE + d] = v.z;
                Bsh[(r4 + 3) * BS_STRIDE + d] = v.w;
            }
            __syncthreads();

            float acc[4][8];
#pragma unroll
            for (int i = 0; i < 4; i++)
#pragma unroll
                for (int j = 0; j < 8; j++) acc[i][j] = 0.f;

#pragma unroll
            for (int r = 0; r < 64; r++) {
                float4 av  = *(const float4*)&Hs[r * HS_STRIDE + a * 4];
                float4 bv0 = *(const float4*)&Bsh[r * BS_STRIDE + b * 8];
                float4 bv1 = *(const float4*)&Bsh[r * BS_STRIDE + b * 8 + 4];
                float aa[4] = {av.x, av.y, av.z, av.w};
                float bb[8] = {bv0.x, bv0.y, bv0.z, bv0.w, bv1.x, bv1.y, bv1.z, bv1.w};
#pragma unroll
                for (int i = 0; i < 4; i++)
#pragma unroll
                    for (int j = 0; j < 8; j++) acc[i][j] += aa[i] * bb[j];
            }

#pragma unroll
            for (int i = 0; i < 4; i++) {
                int t = stok[a * 4 + i];
                if (t < 0) continue;
                float* p = &out[(size_t)t * D_OUT + d0 + b * 8];
                red_v4(p,     acc[i][0], acc[i][1], acc[i][2], acc[i][3]);
                red_v4(p + 4, acc[i][4], acc[i][5], acc[i][6], acc[i][7]);
            }
            __syncthreads();
        }
        __syncthreads();
    }
}

// ============================================================================
// launch
// ============================================================================
extern "C" void kernel_launch(void* const* d_in, const int* in_sizes, int n_in,
                              void* d_out, int out_size)
{
    const float* x   = (const float*)d_in[0];
    const float* Wb  = (const float*)d_in[1];
    const float* bb  = (const float*)d_in[2];
    const float* A   = (const float*)d_in[3];
    const float* Bm  = (const float*)d_in[4];
    const float* Wr  = (const float*)d_in[5];
    const int* topk  = (n_in > 6) ? (const int*)d_in[6] : nullptr;
    float* out       = (float*)d_out;

    (void)in_sizes; (void)out_size;

    __nv_bfloat16 *p_xhi, *p_xlo, *p_whi, *p_wlo;
    cudaGetSymbolAddress((void**)&p_xhi, g_xhi);
    cudaGetSymbolAddress((void**)&p_xlo, g_xlo);
    cudaGetSymbolAddress((void**)&p_whi, g_whi);
    cudaGetSymbolAddress((void**)&p_wlo, g_wlo);

    cudaFuncSetAttribute(k3_mma_gemm, cudaFuncAttributeMaxDynamicSharedMemorySize, SMEM_K3);
    cudaFuncSetAttribute(k4_delta,    cudaFuncAttributeMaxDynamicSharedMemorySize, K4_SMEM);

    int n4x = T_TOK * D_IN / 4, n4w = D_OUT * D_IN / 4;
    k0_convert<<<(n4x + 255) / 256, 256>>>(x,  p_xhi, p_xlo, n4x);
    k0_convert<<<(n4w + 255) / 256, 256>>>(Wb, p_whi, p_wlo, n4w);
    k1_small_gemm<<<dim3(2, T_TOK / 128), 256>>>(x, A, Wr);
    k2_router   <<<T_TOK / 128, 128>>>(topk);
    k3_mma_gemm <<<dim3(D_OUT / 256, T_TOK / 128), 256, SMEM_K3>>>(bb, out);
    k4_delta    <<<N_EXP * 32, 256, K4_SMEM>>>(Bm, out);
}

// round 5
// speedup vs baseline: 1.1138x; 1.1138x over previous
#include <cuda_runtime.h>
#include <cuda_bf16.h>
#include <cstdint>

// Problem constants (fixed by setup_inputs)
#define T_TOK   8192      // B*S = 4*2048
#define D_IN    2048
#define D_OUT   2048
#define R_RANK  64
#define N_EXP   16
#define N_COLS  80        // R + E combined small-GEMM width

// ---------------- device scratch (no allocations allowed) ----------------
__device__ float g_S[T_TOK * N_COLS];        // [token][0..63]=res_hidden, [64..79]=router logits
__device__ int   g_cnt[N_EXP];
__device__ int   g_tok[N_EXP * T_TOK];
__device__ float g_wt [N_EXP * T_TOK];
// hi/lo bf16 copies for the tensor-core base GEMM
__device__ __nv_bfloat16 g_xhi[T_TOK * D_IN];
__device__ __nv_bfloat16 g_xlo[T_TOK * D_IN];
__device__ __nv_bfloat16 g_whi[D_OUT * D_IN];
__device__ __nv_bfloat16 g_wlo[D_OUT * D_IN];

// ---------------- helpers ----------------
__device__ __forceinline__ uint32_t smem_u32(const void* p) {
    uint32_t a;
    asm("{ .reg .u64 t; cvta.to.shared.u64 t, %1; cvt.u32.u64 %0, t; }" : "=r"(a) : "l"(p));
    return a;
}
__device__ __forceinline__ void cp16(uint32_t s, const void* g) {
    asm volatile("cp.async.cg.shared.global [%0], [%1], 16;" :: "r"(s), "l"(g) : "memory");
}
__device__ __forceinline__ void ldmatrix_x4(uint32_t* r, uint32_t addr) {
    asm volatile("ldmatrix.sync.aligned.m8n8.x4.shared.b16 {%0,%1,%2,%3}, [%4];"
                 : "=r"(r[0]), "=r"(r[1]), "=r"(r[2]), "=r"(r[3]) : "r"(addr));
}
__device__ __forceinline__ void mma16816(float* c, const uint32_t* a, uint32_t b0, uint32_t b1) {
    asm volatile(
        "mma.sync.aligned.m16n8k16.row.col.f32.bf16.bf16.f32 "
        "{%0,%1,%2,%3}, {%4,%5,%6,%7}, {%8,%9}, {%0,%1,%2,%3};"
        : "+f"(c[0]), "+f"(c[1]), "+f"(c[2]), "+f"(c[3])
        : "r"(a[0]), "r"(a[1]), "r"(a[2]), "r"(a[3]), "r"(b0), "r"(b1));
}
__device__ __forceinline__ void red_v4(float* p, float x, float y, float z, float w) {
    asm volatile("red.global.add.v4.f32 [%0], {%1,%2,%3,%4};"
                 :: "l"(p), "f"(x), "f"(y), "f"(z), "f"(w) : "memory");
}
#define CP_COMMIT() asm volatile("cp.async.commit_group;" ::: "memory")
#define CP_WAIT(n)  asm volatile("cp.async.wait_group %0;" :: "n"(n) : "memory")

// ============================================================================
// Kernel 0: fp32 -> (hi, lo) bf16 split
// ============================================================================
__global__ __launch_bounds__(256) void k0_convert(
    const float* __restrict__ src, __nv_bfloat16* __restrict__ hi,
    __nv_bfloat16* __restrict__ lo, int n4)
{
    int i = blockIdx.x * blockDim.x + threadIdx.x;
    if (i >= n4) return;
    float4 v = *(const float4*)&src[(size_t)i * 4];
    __nv_bfloat16 h[4], l[4];
    float vv[4] = {v.x, v.y, v.z, v.w};
#pragma unroll
    for (int j = 0; j < 4; j++) {
        h[j] = __float2bfloat16_rn(vv[j]);
        l[j] = __float2bfloat16_rn(vv[j] - __bfloat162float(h[j]));
    }
    *(uint2*)&hi[(size_t)i * 4] = *(uint2*)h;
    *(uint2*)&lo[(size_t)i * 4] = *(uint2*)l;
}

// ============================================================================
// Kernel 1: S = x @ [A^T | W_router^T]  (fp32 SIMT)
// ============================================================================
__global__ __launch_bounds__(256) void k1_small_gemm(
    const float* __restrict__ x,
    const float* __restrict__ A,
    const float* __restrict__ Wr)
{
    __shared__ float xs[128][68];
    __shared__ float ws[40][68];

    const int tid = threadIdx.x;
    if (blockIdx.x == 0 && blockIdx.y == 0 && tid < N_EXP) g_cnt[tid] = 0;

    const int m0 = blockIdx.y * 128;
    const int c0 = blockIdx.x * 40;
    const int tg = tid >> 3;
    const int cg = tid & 7;

    float acc[4][5];
#pragma unroll
    for (int i = 0; i < 4; i++)
#pragma unroll
        for (int j = 0; j < 5; j++) acc[i][j] = 0.f;

    for (int k0 = 0; k0 < D_IN; k0 += 64) {
#pragma unroll
        for (int it = 0; it < 8; it++) {
            int q = tid + it * 256;
            int row = q >> 4;
            int kc = (q & 15) << 2;
            float4 v = *(const float4*)&x[(size_t)(m0 + row) * D_IN + k0 + kc];
            *(float4*)&xs[row][kc] = v;
        }
        for (int q = tid; q < 40 * 16; q += 256) {
            int col = q >> 4;
            int kc = (q & 15) << 2;
            int gc = c0 + col;
            const float* src = (gc < R_RANK) ? (A + (size_t)gc * D_IN)
                                             : (Wr + (size_t)(gc - R_RANK) * D_IN);
            float4 v = *(const float4*)&src[k0 + kc];
            *(float4*)&ws[col][kc] = v;
        }
        __syncthreads();

#pragma unroll 16
        for (int kk = 0; kk < 64; kk++) {
            float av[4], bv[5];
#pragma unroll
            for (int i = 0; i < 4; i++) av[i] = xs[tg * 4 + i][kk];
#pragma unroll
            for (int j = 0; j < 5; j++) bv[j] = ws[cg * 5 + j][kk];
#pragma unroll
            for (int i = 0; i < 4; i++)
#pragma unroll
                for (int j = 0; j < 5; j++) acc[i][j] += av[i] * bv[j];
        }
        __syncthreads();
    }

#pragma unroll
    for (int i = 0; i < 4; i++) {
        size_t base = (size_t)(m0 + tg * 4 + i) * N_COLS + c0 + cg * 5;
#pragma unroll
        for (int j = 0; j < 5; j++) g_S[base + j] = acc[i][j];
    }
}

// ============================================================================
// Kernel 2: softmax + top-k + scatter
// ============================================================================
__global__ __launch_bounds__(128) void k2_router(const int* __restrict__ topk_ptr)
{
    int t = blockIdx.x * blockDim.x + threadIdx.x;
    if (t >= T_TOK) return;

    float p[N_EXP];
    float mx = -1e30f;
#pragma unroll
    for (int e = 0; e < N_EXP; e++) {
        p[e] = g_S[(size_t)t * N_COLS + R_RANK + e];
        mx = fmaxf(mx, p[e]);
    }
    float sum = 0.f;
#pragma unroll
    for (int e = 0; e < N_EXP; e++) { p[e] = __expf(p[e] - mx); sum += p[e]; }
    float inv = 1.f / sum;
#pragma unroll
    for (int e = 0; e < N_EXP; e++) p[e] *= inv;

    int k = topk_ptr ? *topk_ptr : 2;

    if (k > 0 && k < N_EXP) {
        unsigned sel = 0;
        float ssum = 0.f;
        for (int it = 0; it < k; it++) {
            int best = -1; float bv = -1.f;
#pragma unroll
            for (int e = 0; e < N_EXP; e++)
                if (!((sel >> e) & 1u) && p[e] > bv) { bv = p[e]; best = e; }
            sel |= 1u << best;
            ssum += bv;
        }
        float denom = 1.f / (ssum + 1e-6f);
#pragma unroll
        for (int e = 0; e < N_EXP; e++) {
            if ((sel >> e) & 1u) {
                float w = p[e] * denom;
                int slot = atomicAdd(&g_cnt[e], 1);
                g_tok[e * T_TOK + slot] = t;
                g_wt [e * T_TOK + slot] = w;
            }
        }
    } else {
#pragma unroll
        for (int e = 0; e < N_EXP; e++) {
            int slot = atomicAdd(&g_cnt[e], 1);
            g_tok[e * T_TOK + slot] = t;
            g_wt [e * T_TOK + slot] = p[e];
        }
    }
}

// ============================================================================
// Kernel 3: base GEMM via mma.sync bf16 hi/lo (3-term accumulation)
// CTA tile 128x128, BK=32, 8 warps (2x4), warp tile 64x32, 2-stage cp.async.
// ldmatrix.x4 fragment loads; smem row stride 80B -> conflict-free.
// ============================================================================
#define BK       32
#define NCHUNK   (D_IN / BK)                 // 64
#define MAT_BYTES (128 * 80)                 // 10240
#define STAGE_BYTES (4 * MAT_BYTES)          // 40960
#define SMEM_DYN (2 * STAGE_BYTES)           // 81920

__global__ __launch_bounds__(256, 2) void k3_mma_gemm(
    const float* __restrict__ bias, float* __restrict__ out)
{
    extern __shared__ char sm[];
    const int tid  = threadIdx.x;
    const int wid  = tid >> 5;
    const int lane = tid & 31;
    const int g    = lane >> 2;      // group id 0..7
    const int t4   = lane & 3;       // thread-in-group 0..3

    const int m0 = blockIdx.y * 128;
    const int n0 = blockIdx.x * 128;
    const int wm = (wid >> 2) * 64;  // warp M offset within CTA
    const int wn = (wid & 3) * 32;   // warp N offset within CTA

    const uint32_t sbase = smem_u32(sm);

    // ldmatrix per-lane address components
    // A x4: quads = (m-half, k-half): rows 0-7 / 8-15 of the 16-row tile, k bytes 0/16
    const int a_row = ((lane >> 3) & 1) * 8 + (lane & 7);
    const int a_kb  = (lane >> 4) * 16;
    // B x4 (2 n-tiles per op): quads = (n 8-row tile, k-half)
    const int b_row = ((lane >> 4) & 1) * 8 + (lane & 7);
    const int b_kb  = ((lane >> 3) & 1) * 16;

    float acc[4][4][4];
#pragma unroll
    for (int mi = 0; mi < 4; mi++)
#pragma unroll
        for (int ni = 0; ni < 4; ni++)
#pragma unroll
            for (int r = 0; r < 4; r++) acc[mi][ni][r] = 0.f;

    // ---- async load of one k-chunk into stage p ----
    auto load_chunk = [&](int c) {
        const int p  = c & 1;
        const int k0 = c * BK;
#pragma unroll
        for (int it = 0; it < 8; it++) {
            int q    = tid + it * 256;          // 0..2047
            int mat  = q >> 9;                  // 0..3: Ahi, Alo, Bhi, Blo
            int row  = (q >> 2) & 127;
            int quad = q & 3;
            const __nv_bfloat16* src =
                (mat == 0) ? g_xhi : (mat == 1) ? g_xlo : (mat == 2) ? g_whi : g_wlo;
            int grow = ((mat < 2) ? m0 : n0) + row;
            uint32_t saddr = sbase + p * STAGE_BYTES + mat * MAT_BYTES
                           + row * 80 + quad * 16;
            cp16(saddr, &src[(size_t)grow * D_IN + k0 + quad * 8]);
        }
        CP_COMMIT();
    };

    load_chunk(0);

    for (int c = 0; c < NCHUNK; c++) {
        if (c + 1 < NCHUNK) { load_chunk(c + 1); CP_WAIT(1); }
        else { CP_WAIT(0); }
        __syncthreads();

        const uint32_t stg = sbase + (c & 1) * STAGE_BYTES;
        const uint32_t sAh = stg;
        const uint32_t sAl = stg + MAT_BYTES;
        const uint32_t sBh = stg + 2 * MAT_BYTES;
        const uint32_t sBl = stg + 3 * MAT_BYTES;

#pragma unroll
        for (int ks = 0; ks < 2; ks++) {
            const uint32_t kso = ks * 32;

            uint32_t aH[4][4], aL[4][4];
#pragma unroll
            for (int mi = 0; mi < 4; mi++) {
                uint32_t aoff = (uint32_t)((wm + mi * 16 + a_row) * 80) + kso + a_kb;
                ldmatrix_x4(aH[mi], sAh + aoff);
                ldmatrix_x4(aL[mi], sAl + aoff);
            }
            uint32_t bH[4][2], bL[4][2];
#pragma unroll
            for (int nj = 0; nj < 2; nj++) {
                uint32_t boff = (uint32_t)((wn + nj * 16 + b_row) * 80) + kso + b_kb;
                uint32_t th[4], tl[4];
                ldmatrix_x4(th, sBh + boff);
                ldmatrix_x4(tl, sBl + boff);
                bH[nj * 2][0] = th[0]; bH[nj * 2][1] = th[1];
                bH[nj * 2 + 1][0] = th[2]; bH[nj * 2 + 1][1] = th[3];
                bL[nj * 2][0] = tl[0]; bL[nj * 2][1] = tl[1];
                bL[nj * 2 + 1][0] = tl[2]; bL[nj * 2 + 1][1] = tl[3];
            }

            // 3-term accumulation; inner loop over mi so consecutive MMAs
            // target independent accumulators (no RAW chain on C).
#pragma unroll
            for (int ni = 0; ni < 4; ni++) {
#pragma unroll
                for (int mi = 0; mi < 4; mi++)
                    mma16816(acc[mi][ni], aH[mi], bH[ni][0], bH[ni][1]);   // hi*hi
#pragma unroll
                for (int mi = 0; mi < 4; mi++)
                    mma16816(acc[mi][ni], aH[mi], bL[ni][0], bL[ni][1]);   // hi*lo
#pragma unroll
                for (int mi = 0; mi < 4; mi++)
                    mma16816(acc[mi][ni], aL[mi], bH[ni][0], bH[ni][1]);   // lo*hi
            }
        }
        __syncthreads();
    }

    // ---- epilogue: bias add + store ----
#pragma unroll
    for (int mi = 0; mi < 4; mi++) {
        int row = m0 + wm + mi * 16 + g;
#pragma unroll
        for (int ni = 0; ni < 4; ni++) {
            int col = n0 + wn + ni * 8 + t4 * 2;
            float2 bv = *(const float2*)&bias[col];
            float2 o0, o1;
            o0.x = acc[mi][ni][0] + bv.x;
            o0.y = acc[mi][ni][1] + bv.y;
            o1.x = acc[mi][ni][2] + bv.x;
            o1.y = acc[mi][ni][3] + bv.y;
            *(float2*)&out[(size_t)row * D_OUT + col]       = o0;
            *(float2*)&out[(size_t)(row + 8) * D_OUT + col] = o1;
        }
    }
}

// ============================================================================
// Kernel 4: delta — expert-grouped, block = (expert, 64-token tile), d-loop
// inside (H loaded once). 4 tok x 8 d microtile. red.v4 accumulation.
// ============================================================================
#define HS_STRIDE  68
#define BS_STRIDE  132
#define K4_SMEM    (64 * HS_STRIDE * 4 + 64 * BS_STRIDE * 4 + 64 * 4)  // 51968

__global__ __launch_bounds__(256) void k4_delta(
    const float* __restrict__ Bm,
    float* __restrict__ out)
{
    extern __shared__ float sm4[];
    float* Hs  = sm4;                          // [64][HS_STRIDE]  (r-major, w-scaled)
    float* Bsh = sm4 + 64 * HS_STRIDE;         // [64][BS_STRIDE]  (r-major)
    int*   stok = (int*)(sm4 + 64 * HS_STRIDE + 64 * BS_STRIDE);

    const int e     = blockIdx.x >> 5;         // 16 experts
    const int stile = blockIdx.x & 31;         // 32 token tiles
    const int cnt   = g_cnt[e];
    const int tid   = threadIdx.x;

    if (stile * 64 >= cnt) return;

    const int a = tid >> 4;    // 0..15 token group (4 tokens)
    const int b = tid & 15;    // 0..15 d group (8 d)

    for (int s0 = stile * 64; s0 < cnt; s0 += 32 * 64) {
        // ---- load H tile (64 slots x 64 r), transpose, scale by weight ----
#pragma unroll
        for (int it = 0; it < 4; it++) {
            int q    = tid + it * 256;
            int slot = q >> 4;
            int r4   = (q & 15) << 2;
            int s    = s0 + slot;
            float4 v = make_float4(0.f, 0.f, 0.f, 0.f);
            float  w = 0.f;
            int    t = -1;
            if (s < cnt) {
                t = g_tok[e * T_TOK + s];
                w = g_wt [e * T_TOK + s];
                v = *(const float4*)&g_S[(size_t)t * N_COLS + r4];
            }
            Hs[(r4 + 0) * HS_STRIDE + slot] = v.x * w;
            Hs[(r4 + 1) * HS_STRIDE + slot] = v.y * w;
            Hs[(r4 + 2) * HS_STRIDE + slot] = v.z * w;
            Hs[(r4 + 3) * HS_STRIDE + slot] = v.w * w;
            if (r4 == 0) stok[slot] = t;
        }
        __syncthreads();

        for (int d0 = 0; d0 < D_OUT; d0 += 128) {
            // ---- load B chunk (128 d x 64 r), transpose into [r][d] ----
#pragma unroll
            for (int it = 0; it < 8; it++) {
                int q  = tid + it * 256;
                int d  = q & 127;
                int r4 = (q >> 7) << 2;
                float4 v = *(const float4*)&Bm[((size_t)e * D_OUT + d0 + d) * R_RANK + r4];
                Bsh[(r4 + 0) * BS_STRIDE + d] = v.x;
                Bsh[(r4 + 1) * BS_STRIDE + d] = v.y;
                Bsh[(r4 + 2) * BS_STRIDE + d] = v.z;
                Bsh[(r4 + 3) * BS_STRIDE + d] = v.w;
            }
            __syncthreads();

            float acc[4][8];
#pragma unroll
            for (int i = 0; i < 4; i++)
#pragma unroll
                for (int j = 0; j < 8; j++) acc[i][j] = 0.f;

#pragma unroll
            for (int r = 0; r < 64; r++) {
                float4 av  = *(const float4*)&Hs[r * HS_STRIDE + a * 4];
                float4 bv0 = *(const float4*)&Bsh[r * BS_STRIDE + b * 8];
                float4 bv1 = *(const float4*)&Bsh[r * BS_STRIDE + b * 8 + 4];
                float aa[4] = {av.x, av.y, av.z, av.w};
                float bb[8] = {bv0.x, bv0.y, bv0.z, bv0.w, bv1.x, bv1.y, bv1.z, bv1.w};
#pragma unroll
                for (int i = 0; i < 4; i++)
#pragma unroll
                    for (int j = 0; j < 8; j++) acc[i][j] += aa[i] * bb[j];
            }

#pragma unroll
            for (int i = 0; i < 4; i++) {
                int t = stok[a * 4 + i];
                if (t < 0) continue;
                float* p = &out[(size_t)t * D_OUT + d0 + b * 8];
                red_v4(p,     acc[i][0], acc[i][1], acc[i][2], acc[i][3]);
                red_v4(p + 4, acc[i][4], acc[i][5], acc[i][6], acc[i][7]);
            }
            __syncthreads();
        }
        __syncthreads();
    }
}

// ============================================================================
// launch
// ============================================================================
extern "C" void kernel_launch(void* const* d_in, const int* in_sizes, int n_in,
                              void* d_out, int out_size)
{
    const float* x   = (const float*)d_in[0];
    const float* Wb  = (const float*)d_in[1];
    const float* bb  = (const float*)d_in[2];
    const float* A   = (const float*)d_in[3];
    const float* Bm  = (const float*)d_in[4];
    const float* Wr  = (const float*)d_in[5];
    const int* topk  = (n_in > 6) ? (const int*)d_in[6] : nullptr;
    float* out       = (float*)d_out;

    (void)in_sizes; (void)out_size;

    __nv_bfloat16 *p_xhi, *p_xlo, *p_whi, *p_wlo;
    cudaGetSymbolAddress((void**)&p_xhi, g_xhi);
    cudaGetSymbolAddress((void**)&p_xlo, g_xlo);
    cudaGetSymbolAddress((void**)&p_whi, g_whi);
    cudaGetSymbolAddress((void**)&p_wlo, g_wlo);

    cudaFuncSetAttribute(k3_mma_gemm, cudaFuncAttributeMaxDynamicSharedMemorySize, SMEM_DYN);
    cudaFuncSetAttribute(k4_delta,    cudaFuncAttributeMaxDynamicSharedMemorySize, K4_SMEM);

    int n4x = T_TOK * D_IN / 4, n4w = D_OUT * D_IN / 4;
    k0_convert<<<(n4x + 255) / 256, 256>>>(x,  p_xhi, p_xlo, n4x);
    k0_convert<<<(n4w + 255) / 256, 256>>>(Wb, p_whi, p_wlo, n4w);
    k1_small_gemm<<<dim3(2, T_TOK / 128), 256>>>(x, A, Wr);
    k2_router   <<<T_TOK / 128, 128>>>(topk);
    k3_mma_gemm <<<dim3(D_OUT / 128, T_TOK / 128), 256, SMEM_DYN>>>(bb, out);
    k4_delta    <<<N_EXP * 32, 256, K4_SMEM>>>(Bm, out);
}